// round 15
// baseline (speedup 1.0000x reference)
#include <cuda_runtime.h>
#include <stdint.h>

#define D 128
#define MAX_N 50000
#define MAX_E 500000
#define EPB 32      // edges (or nodes) per block
#define RS 36       // row stride floats (32 + 4 pad); 144B keeps 16B alignment

// ---------------- scratch (no allocation allowed) ----------------
__device__ float g_agg_h[(size_t)MAX_N * D];   // segment_sum(edge_feat, row)
__device__ float g_agg_c[MAX_N * 3];           // segment_sum(trans, row)
__device__ float g_cnt[MAX_N];                 // per-row edge count
__device__ int   g_idx64;                      // 1 if edge_index is int64

typedef unsigned long long ull;

// ---------------- packed f32x2 helpers ----------------
#define PACK2(d, lo, hi)   asm("mov.b64 %0, {%1, %2};" : "=l"(d) : "r"(lo), "r"(hi))
#define UNPACK2(lo, hi, s) asm("mov.b64 {%0, %1}, %2;" : "=r"(lo), "=r"(hi) : "l"(s))
#define FMA2(d, a, b, c)   asm("fma.rn.f32x2 %0, %1, %2, %3;" : "=l"(d) : "l"(a), "l"(b), "l"(c))
#define ADD2(d, a, b)      asm("add.rn.f32x2 %0, %1, %2;" : "=l"(d) : "l"(a), "l"(b))
#define MUL2(d, a, b)      asm("mul.rn.f32x2 %0, %1, %2;" : "=l"(d) : "l"(a), "l"(b))

__device__ __forceinline__ float siluf(float x) { return x / (1.0f + __expf(-x)); }
__device__ __forceinline__ float sigm(float x)  { return 1.0f / (1.0f + __expf(-x)); }

__device__ __forceinline__ ull dup2(float x) {
    ull r; uint32_t u = __float_as_uint(x);
    PACK2(r, u, u);
    return r;
}
__device__ __forceinline__ ull pack2f(float a, float b) {
    ull r; PACK2(r, __float_as_uint(a), __float_as_uint(b));
    return r;
}
__device__ __forceinline__ ull silu2(ull x) {
    uint32_t a, b; UNPACK2(a, b, x);
    uint32_t u0 = __float_as_uint(siluf(__uint_as_float(a)));
    uint32_t u1 = __float_as_uint(siluf(__uint_as_float(b)));
    ull r; PACK2(r, u0, u1);
    return r;
}
__device__ __forceinline__ void st2(float* p, ull x) {
    uint32_t a, b; UNPACK2(a, b, x);
    *(float2*)p = make_float2(__uint_as_float(a), __uint_as_float(b));
}
__device__ __forceinline__ float lo2(ull x) { uint32_t a, b; UNPACK2(a, b, x); return __uint_as_float(a); }
__device__ __forceinline__ float hi2(ull x) { uint32_t a, b; UNPACK2(a, b, x); return __uint_as_float(b); }

__device__ __forceinline__ ull shflx2(ull v, int m) {
    uint32_t a, b; UNPACK2(a, b, v);
    a = __shfl_xor_sync(0xffffffffu, a, m);
    b = __shfl_xor_sync(0xffffffffu, b, m);
    ull r; PACK2(r, a, b);
    return r;
}

// 2D-register-tiled GEMM slice: lane (fg=lane>>2, eg=lane&3) accumulates a
// 4-feature x 8-edge tile. Per k: ONE float4 weight LDG (128B unique/warp,
// coalescer-deduped) + TWO ulonglong2 activation LDS (128B unique/warp,
// broadcast-merged) feed 16 FFMA2 -> FMA-bound, not crossbar-bound.
// in is [K][RS] (k-major), W is [K][D] row-major.
template<int K>
__device__ __forceinline__ void mm4(const float (*__restrict__ in)[RS],
                                    const float* __restrict__ W,
                                    int fbase, int ebase, ull acc[4][4]) {
    const float* wp = W + fbase;
    const float* rp = &in[0][ebase];
    float4 w = *(const float4*)wp;  wp += D;
    ulonglong2 ua = *(const ulonglong2*)rp;
    ulonglong2 ub = *(const ulonglong2*)(rp + 4);
    rp += RS;
#pragma unroll 2
    for (int k = 0; k < K - 1; k++) {
        float4 wn = *(const float4*)wp;  wp += D;   // prefetch next k
        ulonglong2 va = *(const ulonglong2*)rp;
        ulonglong2 vb = *(const ulonglong2*)(rp + 4);
        rp += RS;
        ull w0 = dup2(w.x), w1 = dup2(w.y), w2 = dup2(w.z), w3 = dup2(w.w);
        FMA2(acc[0][0], w0, ua.x, acc[0][0]); FMA2(acc[0][1], w0, ua.y, acc[0][1]);
        FMA2(acc[0][2], w0, ub.x, acc[0][2]); FMA2(acc[0][3], w0, ub.y, acc[0][3]);
        FMA2(acc[1][0], w1, ua.x, acc[1][0]); FMA2(acc[1][1], w1, ua.y, acc[1][1]);
        FMA2(acc[1][2], w1, ub.x, acc[1][2]); FMA2(acc[1][3], w1, ub.y, acc[1][3]);
        FMA2(acc[2][0], w2, ua.x, acc[2][0]); FMA2(acc[2][1], w2, ua.y, acc[2][1]);
        FMA2(acc[2][2], w2, ub.x, acc[2][2]); FMA2(acc[2][3], w2, ub.y, acc[2][3]);
        FMA2(acc[3][0], w3, ua.x, acc[3][0]); FMA2(acc[3][1], w3, ua.y, acc[3][1]);
        FMA2(acc[3][2], w3, ub.x, acc[3][2]); FMA2(acc[3][3], w3, ub.y, acc[3][3]);
        w = wn; ua = va; ub = vb;
    }
    {
        ull w0 = dup2(w.x), w1 = dup2(w.y), w2 = dup2(w.z), w3 = dup2(w.w);
        FMA2(acc[0][0], w0, ua.x, acc[0][0]); FMA2(acc[0][1], w0, ua.y, acc[0][1]);
        FMA2(acc[0][2], w0, ub.x, acc[0][2]); FMA2(acc[0][3], w0, ub.y, acc[0][3]);
        FMA2(acc[1][0], w1, ua.x, acc[1][0]); FMA2(acc[1][1], w1, ua.y, acc[1][1]);
        FMA2(acc[1][2], w1, ub.x, acc[1][2]); FMA2(acc[1][3], w1, ub.y, acc[1][3]);
        FMA2(acc[2][0], w2, ua.x, acc[2][0]); FMA2(acc[2][1], w2, ua.y, acc[2][1]);
        FMA2(acc[2][2], w2, ub.x, acc[2][2]); FMA2(acc[2][3], w2, ub.y, acc[2][3]);
        FMA2(acc[3][0], w3, ua.x, acc[3][0]); FMA2(acc[3][1], w3, ua.y, acc[3][1]);
        FMA2(acc[3][2], w3, ub.x, acc[3][2]); FMA2(acc[3][3], w3, ub.y, acc[3][3]);
    }
}

#define ZERO_ACC(acc) do { \
    _Pragma("unroll") for (int _f = 0; _f < 4; _f++) \
    _Pragma("unroll") for (int _p = 0; _p < 4; _p++) acc[_f][_p] = 0ull; } while (0)

// Detect whether edge_index is int64 (high words all zero) or int32.
__global__ void detect_kernel(const int* __restrict__ ei) {
    if (threadIdx.x == 0) {
        int nz = 0;
        for (int i = 1; i < 128; i += 2) nz |= ei[i];
        g_idx64 = (nz == 0) ? 1 : 0;
    }
}

__global__ void zero_kernel(int N) {
    long tot = (long)N * D + (long)N * 3 + N;
    long stride = (long)gridDim.x * blockDim.x;
    for (long i = (long)blockIdx.x * blockDim.x + threadIdx.x; i < tot; i += stride) {
        if (i < (long)N * D)               g_agg_h[i] = 0.0f;
        else if (i < (long)N * D + 3L * N) g_agg_c[i - (long)N * D] = 0.0f;
        else                               g_cnt[i - (long)N * D - 3L * N] = 0.0f;
    }
}

// ---------------- fused edge kernel ----------------
// 128 threads, 32 edges/block. Lane (fg,eg) owns features fbase..fbase+3
// (fbase = 32*warp + 4*fg) x edges ebase..ebase+7 (ebase = 8*eg).
// smem: rows 0-127 h_row -> mij, rows 128-255 h_col -> hid, row 256 radial.
__global__ __launch_bounds__(128, 5) void edge_kernel(
    const float* __restrict__ h, const void* __restrict__ eiv,
    const float* __restrict__ coord,
    const float* __restrict__ We1, const float* __restrict__ be1,
    const float* __restrict__ We2, const float* __restrict__ be2,
    const float* __restrict__ Watt, const float* __restrict__ batt,
    const float* __restrict__ Wc1, const float* __restrict__ bc1,
    const float* __restrict__ Wc2,
    float* __restrict__ out_ef, int E)
{
    __shared__ __align__(16) float in_t[257][RS];
    __shared__ float red_s[4][EPB];
    __shared__ float att_s[EPB];
    __shared__ float cw_s[EPB];
    __shared__ float cd_s[EPB][3];
    __shared__ int   row_s[EPB], col_s[EPB];

    const int t = threadIdx.x;        // 0..127
    const int lane = t & 31;
    const int warp = t >> 5;
    const int eg = lane & 3;
    const int fg = lane >> 2;
    const int fbase = warp * 32 + fg * 4;
    const int ebase = eg * 8;
    const long e0 = (long)blockIdx.x * EPB;
    const int idx64 = g_idx64;

    // edge indices
    if (t < EPB) {
        long e = e0 + t;
        int r = 0, c = 0;
        if (e < E) {
            if (idx64) {
                const long long* ei = (const long long*)eiv;
                r = (int)ei[e];
                c = (int)ei[(long)E + e];
            } else {
                const int* ei = (const int*)eiv;
                r = ei[e];
                c = ei[(long)E + e];
            }
        }
        row_s[t] = r;
        col_s[t] = c;
    }
    __syncthreads();

    // gather: thread t fills feature-row t (h_row) and 128+t (h_col)
#pragma unroll 4
    for (int e = 0; e < EPB; e++) {
        long ro = (long)row_s[e] * D;
        long co = (long)col_s[e] * D;
        in_t[t][e]       = h[ro + t];
        in_t[128 + t][e] = h[co + t];
    }
    if (t < EPB * 3) {
        int e = t / 3, d = t % 3;
        cd_s[e][d] = coord[(long)row_s[e] * 3 + d] - coord[(long)col_s[e] * 3 + d];
    }
    __syncthreads();
    if (t < EPB) {
        float x = cd_s[t][0], y = cd_s[t][1], z = cd_s[t][2];
        in_t[256][t] = x * x + y * y + z * z;   // radial
    }
    __syncthreads();

    ull acc[4][4];

    // ---- edge_mlp layer 1: [2D+1] -> D, SiLU -> rows 128-255 ----
    ZERO_ACC(acc);
    mm4<257>(in_t, We1, fbase, ebase, acc);
    __syncthreads();   // all reads done; rows 128-255 become hid storage
    {
        float4 b = *(const float4*)&be1[fbase];
        float bf[4] = {b.x, b.y, b.z, b.w};
#pragma unroll
        for (int f = 0; f < 4; f++) {
            ull bd = dup2(bf[f]);
#pragma unroll
            for (int p = 0; p < 4; p++) {
                ADD2(acc[f][p], acc[f][p], bd);
                st2(&in_t[128 + fbase + f][ebase + 2 * p], silu2(acc[f][p]));
            }
        }
    }
    __syncthreads();

    // ---- edge_mlp layer 2: D -> D, SiLU -> mij rows 0-127; attention partials ----
    ZERO_ACC(acc);
    mm4<128>((const float (*)[RS])(in_t + 128), We2, fbase, ebase, acc);
    {
        float4 b  = *(const float4*)&be2[fbase];
        float4 wa = *(const float4*)&Watt[fbase];
        float bf[4] = {b.x, b.y, b.z, b.w};
        float wf[4] = {wa.x, wa.y, wa.z, wa.w};
        ull s[4] = {0ull, 0ull, 0ull, 0ull};
#pragma unroll
        for (int f = 0; f < 4; f++) {
            ull bd = dup2(bf[f]), wd = dup2(wf[f]);
#pragma unroll
            for (int p = 0; p < 4; p++) {
                ADD2(acc[f][p], acc[f][p], bd);
                ull z = silu2(acc[f][p]);
                st2(&in_t[fbase + f][ebase + 2 * p], z);
                FMA2(s[p], wd, z, s[p]);
            }
        }
        // butterfly over fg (lane bits 2..4)
#pragma unroll
        for (int p = 0; p < 4; p++) {
            ull v = s[p];
            ull r4  = shflx2(v, 4);  ADD2(v, v, r4);
            ull r8  = shflx2(v, 8);  ADD2(v, v, r8);
            ull r16 = shflx2(v, 16); ADD2(v, v, r16);
            if (fg == 0) {
                red_s[warp][ebase + 2 * p]     = lo2(v);
                red_s[warp][ebase + 2 * p + 1] = hi2(v);
            }
        }
    }
    __syncthreads();   // publishes mij + attention partials
    if (t < EPB)
        att_s[t] = sigm(red_s[0][t] + red_s[1][t] + red_s[2][t] + red_s[3][t] + batt[0]);
    __syncthreads();

    // ---- edge_feat = mij * att: coalesced float4 stores + scatter (overlaps) ----
#pragma unroll
    for (int p = 0; p < 4; p++) {
        ull ap = pack2f(att_s[ebase + 2 * p], att_s[ebase + 2 * p + 1]);
        ull ef[4];
#pragma unroll
        for (int f = 0; f < 4; f++) {
            ull mp = *(const ull*)&in_t[fbase + f][ebase + 2 * p];
            MUL2(ef[f], mp, ap);
        }
#pragma unroll
        for (int hh = 0; hh < 2; hh++) {
            long e = e0 + ebase + 2 * p + hh;
            if (e < E) {
                float4 v = hh ? make_float4(hi2(ef[0]), hi2(ef[1]), hi2(ef[2]), hi2(ef[3]))
                              : make_float4(lo2(ef[0]), lo2(ef[1]), lo2(ef[2]), lo2(ef[3]));
                *(float4*)&out_ef[e * D + fbase] = v;
                long rb = (long)row_s[ebase + 2 * p + hh] * D + fbase;
                atomicAdd(&g_agg_h[rb + 0], v.x);
                atomicAdd(&g_agg_h[rb + 1], v.y);
                atomicAdd(&g_agg_h[rb + 2], v.z);
                atomicAdd(&g_agg_h[rb + 3], v.w);
            }
        }
    }

    // ---- coord_mlp: cw = silu(edge_feat @ Wc1 + bc1) @ Wc2 ----
    // edge_feat = att * mij => per-feature dot = att * dot(mij, Wc1col)
    ZERO_ACC(acc);
    mm4<128>(in_t, Wc1, fbase, ebase, acc);
    {
        float4 bc = *(const float4*)&bc1[fbase];
        float4 wc = *(const float4*)&Wc2[fbase];
        float bf[4] = {bc.x, bc.y, bc.z, bc.w};
        float wf[4] = {wc.x, wc.y, wc.z, wc.w};
        ull s[4] = {0ull, 0ull, 0ull, 0ull};
#pragma unroll
        for (int p = 0; p < 4; p++) {
            ull ap = pack2f(att_s[ebase + 2 * p], att_s[ebase + 2 * p + 1]);
#pragma unroll
            for (int f = 0; f < 4; f++) {
                ull tmp;
                FMA2(tmp, ap, acc[f][p], dup2(bf[f]));
                tmp = silu2(tmp);
                FMA2(s[p], dup2(wf[f]), tmp, s[p]);
            }
        }
#pragma unroll
        for (int p = 0; p < 4; p++) {
            ull v = s[p];
            ull r4  = shflx2(v, 4);  ADD2(v, v, r4);
            ull r8  = shflx2(v, 8);  ADD2(v, v, r8);
            ull r16 = shflx2(v, 16); ADD2(v, v, r16);
            if (fg == 0) {
                red_s[warp][ebase + 2 * p]     = lo2(v);
                red_s[warp][ebase + 2 * p + 1] = hi2(v);
            }
        }
    }
    __syncthreads();
    if (t < EPB)
        cw_s[t] = red_s[0][t] + red_s[1][t] + red_s[2][t] + red_s[3][t];
    __syncthreads();

    // ---- trans = clip(coord_diff * cw, +/-10); scatter into agg_c, cnt ----
    if (t < EPB * 3) {
        int e = t / 3, d = t % 3;
        long eg2 = e0 + e;
        if (eg2 < E) {
            float tr = cd_s[e][d] * cw_s[e];
            tr = fminf(10.0f, fmaxf(-10.0f, tr));
            atomicAdd(&g_agg_c[(long)row_s[e] * 3 + d], tr);
        }
    }
    if (t < EPB) {
        long eg2 = e0 + t;
        if (eg2 < E) atomicAdd(&g_cnt[row_s[t]], 1.0f);
    }
}

// ---------------- node kernel: h_out = h + node_mlp([h, agg]) ----------------
// rows 0-127 h (kept for residual), rows 128-255 agg -> hid.
__global__ __launch_bounds__(128, 5) void node_kernel(
    const float* __restrict__ h,
    const float* __restrict__ Wn1, const float* __restrict__ bn1,
    const float* __restrict__ Wn2, const float* __restrict__ bn2,
    float* __restrict__ h_out, int N)
{
    __shared__ __align__(16) float in_t[256][RS];

    const int t = threadIdx.x;
    const int lane = t & 31;
    const int warp = t >> 5;
    const int eg = lane & 3;
    const int fg = lane >> 2;
    const int fbase = warp * 32 + fg * 4;
    const int ebase = eg * 8;
    const long n0 = (long)blockIdx.x * EPB;

#pragma unroll 4
    for (int e = 0; e < EPB; e++) {
        long n = n0 + e;
        if (n >= N) n = N - 1;
        long nb = n * D;
        in_t[t][e]       = h[nb + t];
        in_t[128 + t][e] = g_agg_h[nb + t];
    }
    __syncthreads();

    ull acc[4][4];
    ZERO_ACC(acc);
    mm4<256>(in_t, Wn1, fbase, ebase, acc);
    __syncthreads();   // reads done; rows 128-255 become hid storage
    {
        float4 b = *(const float4*)&bn1[fbase];
        float bf[4] = {b.x, b.y, b.z, b.w};
#pragma unroll
        for (int f = 0; f < 4; f++) {
            ull bd = dup2(bf[f]);
#pragma unroll
            for (int p = 0; p < 4; p++) {
                ADD2(acc[f][p], acc[f][p], bd);
                st2(&in_t[128 + fbase + f][ebase + 2 * p], silu2(acc[f][p]));
            }
        }
    }
    __syncthreads();

    ZERO_ACC(acc);
    mm4<128>((const float (*)[RS])(in_t + 128), Wn2, fbase, ebase, acc);
    {
        float4 b = *(const float4*)&bn2[fbase];
        float bf[4] = {b.x, b.y, b.z, b.w};
#pragma unroll
        for (int p = 0; p < 4; p++) {
            ull r[4];
#pragma unroll
            for (int f = 0; f < 4; f++) {
                ull hp = *(const ull*)&in_t[fbase + f][ebase + 2 * p];  // residual h
                ADD2(r[f], acc[f][p], dup2(bf[f]));
                ADD2(r[f], r[f], hp);
            }
#pragma unroll
            for (int hh = 0; hh < 2; hh++) {
                long n = n0 + ebase + 2 * p + hh;
                if (n < N) {
                    float4 v = hh ? make_float4(hi2(r[0]), hi2(r[1]), hi2(r[2]), hi2(r[3]))
                                  : make_float4(lo2(r[0]), lo2(r[1]), lo2(r[2]), lo2(r[3]));
                    *(float4*)&h_out[n * D + fbase] = v;
                }
            }
        }
    }
}

// ---------------- coord finalize: coord + clip(agg_c / max(cnt,1), +/-10) ----
__global__ void coord_kernel(const float* __restrict__ coord,
                             float* __restrict__ coord_out, int N)
{
    int i = blockIdx.x * blockDim.x + threadIdx.x;
    if (i < N * 3) {
        int n = i / 3;
        float m = g_agg_c[i] / fmaxf(g_cnt[n], 1.0f);
        m = fminf(10.0f, fmaxf(-10.0f, m));
        coord_out[i] = coord[i] + m;
    }
}

// ---------------- launch ----------------
extern "C" void kernel_launch(void* const* d_in, const int* in_sizes, int n_in,
                              void* d_out, int out_size)
{
    const float* h     = (const float*)d_in[0];
    const void*  ei    = d_in[1];
    const float* coord = (const float*)d_in[2];
    const float* We1   = (const float*)d_in[3];
    const float* be1   = (const float*)d_in[4];
    const float* We2   = (const float*)d_in[5];
    const float* be2   = (const float*)d_in[6];
    const float* Watt  = (const float*)d_in[7];
    const float* batt  = (const float*)d_in[8];
    const float* Wc1   = (const float*)d_in[9];
    const float* bc1   = (const float*)d_in[10];
    const float* Wc2   = (const float*)d_in[11];
    const float* Wn1   = (const float*)d_in[12];
    const float* bn1   = (const float*)d_in[13];
    const float* Wn2   = (const float*)d_in[14];
    const float* bn2   = (const float*)d_in[15];

    const int N = in_sizes[0] / D;
    const int E = in_sizes[1] / 2;

    float* out       = (float*)d_out;
    float* h_out     = out;
    float* coord_out = out + (long)N * D;
    float* out_ef    = out + (long)N * D + (long)N * 3;

    detect_kernel<<<1, 32>>>((const int*)ei);
    zero_kernel<<<1024, 256>>>(N);

    int eb = (E + EPB - 1) / EPB;
    edge_kernel<<<eb, 128>>>(h, ei, coord,
                             We1, be1, We2, be2, Watt, batt,
                             Wc1, bc1, Wc2, out_ef, E);

    int nb = (N + EPB - 1) / EPB;
    node_kernel<<<nb, 128>>>(h, Wn1, bn1, Wn2, bn2, h_out, N);

    coord_kernel<<<(N * 3 + 255) / 256, 256>>>(coord, coord_out, N);
}

// round 16
// speedup vs baseline: 1.1077x; 1.1077x over previous
#include <cuda_runtime.h>
#include <stdint.h>

#define D 128
#define MAX_N 50000
#define MAX_E 500000
#define EPB 16
#define RS 20   // padded row stride (floats); multiple of 4 keeps LDS.128 alignment

// ---------------- scratch (no allocation allowed) ----------------
__device__ float g_agg_h[(size_t)MAX_N * D];   // segment_sum(edge_feat, row)
__device__ float g_P[(size_t)MAX_N * D];       // h @ We1[0:128]    (per-node layer-1 partial)
__device__ float g_Q[(size_t)MAX_N * D];       // h @ We1[128:256]  (per-node layer-1 partial)
__device__ float g_agg_c[MAX_N * 3];           // segment_sum(trans, row)
__device__ float g_cnt[MAX_N];                 // per-row edge count
__device__ int   g_idx64;                      // 1 if edge_index is int64

typedef unsigned long long ull;

// ---------------- packed f32x2 helpers ----------------
#define PACK2(d, lo, hi)   asm("mov.b64 %0, {%1, %2};" : "=l"(d) : "r"(lo), "r"(hi))
#define UNPACK2(lo, hi, s) asm("mov.b64 {%0, %1}, %2;" : "=r"(lo), "=r"(hi) : "l"(s))
#define FMA2(d, a, b, c)   asm("fma.rn.f32x2 %0, %1, %2, %3;" : "=l"(d) : "l"(a), "l"(b), "l"(c))
#define ADD2(d, a, b)      asm("add.rn.f32x2 %0, %1, %2;" : "=l"(d) : "l"(a), "l"(b))
#define MUL2(d, a, b)      asm("mul.rn.f32x2 %0, %1, %2;" : "=l"(d) : "l"(a), "l"(b))

__device__ __forceinline__ float siluf(float x) { return x / (1.0f + __expf(-x)); }
__device__ __forceinline__ float sigm(float x)  { return 1.0f / (1.0f + __expf(-x)); }

__device__ __forceinline__ ull dup2(float x) {
    ull r; uint32_t u = __float_as_uint(x);
    PACK2(r, u, u);
    return r;
}
__device__ __forceinline__ ull pack2f(float a, float b) {
    ull r; PACK2(r, __float_as_uint(a), __float_as_uint(b));
    return r;
}
__device__ __forceinline__ ull silu2(ull x) {
    uint32_t a, b; UNPACK2(a, b, x);
    uint32_t u0 = __float_as_uint(siluf(__uint_as_float(a)));
    uint32_t u1 = __float_as_uint(siluf(__uint_as_float(b)));
    ull r; PACK2(r, u0, u1);
    return r;
}
__device__ __forceinline__ void st2(float* p, ull x) {
    uint32_t a, b; UNPACK2(a, b, x);
    *(float2*)p = make_float2(__uint_as_float(a), __uint_as_float(b));
}
__device__ __forceinline__ float lo2(ull x) { uint32_t a, b; UNPACK2(a, b, x); return __uint_as_float(a); }
__device__ __forceinline__ float hi2(ull x) { uint32_t a, b; UNPACK2(a, b, x); return __uint_as_float(b); }

__device__ __forceinline__ float wsum(float v) {
    v += __shfl_xor_sync(0xffffffffu, v, 16);
    v += __shfl_xor_sync(0xffffffffu, v, 8);
    v += __shfl_xor_sync(0xffffffffu, v, 4);
    v += __shfl_xor_sync(0xffffffffu, v, 2);
    v += __shfl_xor_sync(0xffffffffu, v, 1);
    return v;
}

// F=2 rank-1-per-k outer product over 16 edges (8 f32x2 pairs) for ADJACENT
// features f2 and f2+1 (one float2 weight LDG per k, software-prefetched).
// in is [K][RS] transposed (k-major), W is [K][D] row-major.  (R11 structure.)
template<int K>
__device__ __forceinline__ void mm2(const float (*__restrict__ in)[RS],
                                    const float* __restrict__ W,
                                    int f2, ull a0[8], ull a1[8]) {
    const float* wp = W + f2;
    float2 w = *(const float2*)wp;
    wp += D;
#pragma unroll 4
    for (int k = 0; k < K - 1; k++) {
        float2 wn = *(const float2*)wp;     // prefetch next k's weights
        wp += D;
        ull w0 = dup2(w.x), w1 = dup2(w.y);
        const float* rp = in[k];
#pragma unroll
        for (int q = 0; q < 4; q++) {
            ulonglong2 u = *(const ulonglong2*)(rp + 4 * q);
            FMA2(a0[2 * q],     w0, u.x, a0[2 * q]);
            FMA2(a0[2 * q + 1], w0, u.y, a0[2 * q + 1]);
            FMA2(a1[2 * q],     w1, u.x, a1[2 * q]);
            FMA2(a1[2 * q + 1], w1, u.y, a1[2 * q + 1]);
        }
        w = wn;
    }
    {
        ull w0 = dup2(w.x), w1 = dup2(w.y);
        const float* rp = in[K - 1];
#pragma unroll
        for (int q = 0; q < 4; q++) {
            ulonglong2 u = *(const ulonglong2*)(rp + 4 * q);
            FMA2(a0[2 * q],     w0, u.x, a0[2 * q]);
            FMA2(a0[2 * q + 1], w0, u.y, a0[2 * q + 1]);
            FMA2(a1[2 * q],     w1, u.x, a1[2 * q]);
            FMA2(a1[2 * q + 1], w1, u.y, a1[2 * q + 1]);
        }
    }
}

// Detect whether edge_index is int64 (high words all zero) or int32.
__global__ void detect_kernel(const int* __restrict__ ei) {
    if (threadIdx.x == 0) {
        int nz = 0;
        for (int i = 1; i < 128; i += 2) nz |= ei[i];
        g_idx64 = (nz == 0) ? 1 : 0;
    }
}

__global__ void zero_kernel(int N) {
    long tot = (long)N * D + (long)N * 3 + N;
    long stride = (long)gridDim.x * blockDim.x;
    for (long i = (long)blockIdx.x * blockDim.x + threadIdx.x; i < tot; i += stride) {
        if (i < (long)N * D)               g_agg_h[i] = 0.0f;
        else if (i < (long)N * D + 3L * N) g_agg_c[i - (long)N * D] = 0.0f;
        else                               g_cnt[i - (long)N * D - 3L * N] = 0.0f;
    }
}

// ---------------- pre kernel: per-node layer-1 partials ----------------
// P[n] = h[n] @ We1[0:128],  Q[n] = h[n] @ We1[128:256].  The per-edge
// layer-1 GEMM (K=257 over 500K edges) becomes P[row]+Q[col]+rad*wr+b.
__global__ __launch_bounds__(64, 10) void pre_kernel(
    const float* __restrict__ h, const float* __restrict__ We1, int N)
{
    __shared__ __align__(16) float in_t[128][RS];

    const int t = threadIdx.x;     // 0..63
    const int f2 = 2 * t;
    const long n0 = (long)blockIdx.x * EPB;

#pragma unroll
    for (int e = 0; e < EPB; e++) {
        long n = n0 + e;
        if (n >= N) n = N - 1;
        in_t[t][e]      = h[n * D + t];
        in_t[t + 64][e] = h[n * D + t + 64];
    }
    __syncthreads();

    ull a0[8], a1[8];

    // P = h @ We1[0:128]
#pragma unroll
    for (int j = 0; j < 8; j++) { a0[j] = 0ull; a1[j] = 0ull; }
    mm2<128>(in_t, We1, f2, a0, a1);
#pragma unroll
    for (int j = 0; j < 8; j++) {
        long nA = n0 + 2 * j, nB = nA + 1;
        if (nA < N) *(float2*)&g_P[nA * D + f2] = make_float2(lo2(a0[j]), lo2(a1[j]));
        if (nB < N) *(float2*)&g_P[nB * D + f2] = make_float2(hi2(a0[j]), hi2(a1[j]));
    }

    // Q = h @ We1[128:256]
#pragma unroll
    for (int j = 0; j < 8; j++) { a0[j] = 0ull; a1[j] = 0ull; }
    mm2<128>(in_t, We1 + 128 * D, f2, a0, a1);
#pragma unroll
    for (int j = 0; j < 8; j++) {
        long nA = n0 + 2 * j, nB = nA + 1;
        if (nA < N) *(float2*)&g_Q[nA * D + f2] = make_float2(lo2(a0[j]), lo2(a1[j]));
        if (nB < N) *(float2*)&g_Q[nB * D + f2] = make_float2(hi2(a0[j]), hi2(a1[j]));
    }
}

// ---------------- fused edge kernel ----------------
// 64 threads; thread t owns features 2t and 2t+1; 16 edges/block as 8 f32x2
// pairs. Layer 1 is now a GATHER: hid = silu(P[row]+Q[col]+rad*wr+b) written
// straight into smem rows 128-255. Rows 0-127 hold mij after layer 2.
__global__ __launch_bounds__(64, 10) void edge_kernel(
    const void* __restrict__ eiv, const float* __restrict__ coord,
    const float* __restrict__ We1, const float* __restrict__ be1,
    const float* __restrict__ We2, const float* __restrict__ be2,
    const float* __restrict__ Watt, const float* __restrict__ batt,
    const float* __restrict__ Wc1, const float* __restrict__ bc1,
    const float* __restrict__ Wc2,
    float* __restrict__ out_ef, int E)
{
    __shared__ __align__(16) float in_t[256][RS];
    __shared__ float red_s[2][EPB];
    __shared__ float att_s[EPB];
    __shared__ float cw_s[EPB];
    __shared__ float rad_s[EPB];
    __shared__ float cd_s[EPB][3];
    __shared__ int   row_s[EPB], col_s[EPB];

    const int t = threadIdx.x;     // 0..63
    const int lane = t & 31;
    const int warp = t >> 5;
    const int f2 = 2 * t;          // features f2, f2+1
    const long e0 = (long)blockIdx.x * EPB;
    const int idx64 = g_idx64;

    // edge indices
    if (t < EPB) {
        long e = e0 + t;
        int r = 0, c = 0;
        if (e < E) {
            if (idx64) {
                const long long* ei = (const long long*)eiv;
                r = (int)ei[e];
                c = (int)ei[(long)E + e];
            } else {
                const int* ei = (const int*)eiv;
                r = ei[e];
                c = ei[(long)E + e];
            }
        }
        row_s[t] = r;
        col_s[t] = c;
    }
    __syncthreads();

    if (t < EPB * 3) {
        int e = t / 3, d = t % 3;
        cd_s[e][d] = coord[(long)row_s[e] * 3 + d] - coord[(long)col_s[e] * 3 + d];
    }
    __syncthreads();
    if (t < EPB) {
        float x = cd_s[t][0], y = cd_s[t][1], z = cd_s[t][2];
        rad_s[t] = x * x + y * y + z * z;
    }
    __syncthreads();

    // fused gather + layer-1 epilogue: hid = silu(P[row]+Q[col]+rad*wr+b)
    {
        float wr0 = We1[256 * D + t], wr1 = We1[256 * D + t + 64];
        float b0  = be1[t],           b1  = be1[t + 64];
#pragma unroll
        for (int e = 0; e < EPB; e++) {
            long ro = (long)row_s[e] * D;
            long co = (long)col_s[e] * D;
            float r = rad_s[e];
            in_t[128 + t][e] = siluf(g_P[ro + t]      + g_Q[co + t]      + wr0 * r + b0);
            in_t[192 + t][e] = siluf(g_P[ro + t + 64] + g_Q[co + t + 64] + wr1 * r + b1);
        }
    }
    __syncthreads();

    ull a0[8], a1[8];

    // ---- edge_mlp layer 2: D -> D, SiLU; hid = rows 128-255, mij -> rows 0-127 ----
#pragma unroll
    for (int j = 0; j < 8; j++) { a0[j] = 0ull; a1[j] = 0ull; }
    mm2<128>((const float (*)[RS])(in_t + 128), We2, f2, a0, a1);
    {
        float2 b = *(const float2*)&be2[f2];
        ull b0 = dup2(b.x), b1 = dup2(b.y);
#pragma unroll
        for (int j = 0; j < 8; j++) {
            ADD2(a0[j], a0[j], b0); a0[j] = silu2(a0[j]); st2(&in_t[f2][2 * j], a0[j]);
            ADD2(a1[j], a1[j], b1); a1[j] = silu2(a1[j]); st2(&in_t[f2 + 1][2 * j], a1[j]);
        }
    }

    // ---- attention partials from live accumulators ----
    {
        float2 wa = *(const float2*)&Watt[f2];
        ull wa0 = dup2(wa.x), wa1 = dup2(wa.y);
#pragma unroll
        for (int j = 0; j < 8; j++) {
            ull s; MUL2(s, a0[j], wa0); FMA2(s, a1[j], wa1, s);
            float r0 = wsum(lo2(s));
            float r1 = wsum(hi2(s));
            if (lane == 0) { red_s[warp][2 * j] = r0; red_s[warp][2 * j + 1] = r1; }
        }
    }
    __syncthreads();   // also publishes mij in rows 0-127
    if (t < EPB)
        att_s[t] = sigm(red_s[0][t] + red_s[1][t] + batt[0]);
    __syncthreads();

    // ---- edge_feat = mij * att: write output + scatter early (overlap atomics) ----
#pragma unroll
    for (int j = 0; j < 8; j++) {
        ull ap = pack2f(att_s[2 * j], att_s[2 * j + 1]);
        ull m0 = *(const ull*)&in_t[f2][2 * j];        // feature f2, edges (eA,eB)
        ull m1 = *(const ull*)&in_t[f2 + 1][2 * j];    // feature f2+1
        ull ef0, ef1; MUL2(ef0, m0, ap); MUL2(ef1, m1, ap);
        long eA = e0 + 2 * j, eB = eA + 1;
        if (eA < E) {
            float v0 = lo2(ef0), v1 = lo2(ef1);
            *(float2*)&out_ef[eA * D + f2] = make_float2(v0, v1);
            long rb = (long)row_s[2 * j] * D;
            atomicAdd(&g_agg_h[rb + f2], v0);
            atomicAdd(&g_agg_h[rb + f2 + 1], v1);
        }
        if (eB < E) {
            float v0 = hi2(ef0), v1 = hi2(ef1);
            *(float2*)&out_ef[eB * D + f2] = make_float2(v0, v1);
            long rb = (long)row_s[2 * j + 1] * D;
            atomicAdd(&g_agg_h[rb + f2], v0);
            atomicAdd(&g_agg_h[rb + f2 + 1], v1);
        }
    }

    // ---- coord_mlp: cw = silu(edge_feat @ Wc1 + bc1) @ Wc2 ----
    // edge_feat = att * mij, so dot(edge_feat, Wc1col) = att * dot(mij, Wc1col)
#pragma unroll
    for (int j = 0; j < 8; j++) { a0[j] = 0ull; a1[j] = 0ull; }
    mm2<128>(in_t, Wc1, f2, a0, a1);
    {
        float2 bc = *(const float2*)&bc1[f2];
        float2 wc = *(const float2*)&Wc2[f2];
#pragma unroll
        for (int j = 0; j < 8; j++) {
            float d00 = lo2(a0[j]), d01 = hi2(a0[j]);   // feature f2, edges A/B
            float d10 = lo2(a1[j]), d11 = hi2(a1[j]);   // feature f2+1
            float aA = att_s[2 * j], aB = att_s[2 * j + 1];
            float s0 = siluf(fmaf(aA, d00, bc.x)) * wc.x + siluf(fmaf(aA, d10, bc.y)) * wc.y;
            float s1 = siluf(fmaf(aB, d01, bc.x)) * wc.x + siluf(fmaf(aB, d11, bc.y)) * wc.y;
            float r0 = wsum(s0);
            float r1 = wsum(s1);
            if (lane == 0) { red_s[warp][2 * j] = r0; red_s[warp][2 * j + 1] = r1; }
        }
    }
    __syncthreads();
    if (t < EPB)
        cw_s[t] = red_s[0][t] + red_s[1][t];
    __syncthreads();

    // ---- trans = clip(coord_diff * cw, +/-10); scatter into agg_c, cnt ----
    if (t < EPB * 3) {
        int e = t / 3, d = t % 3;
        long eg = e0 + e;
        if (eg < E) {
            float tr = cd_s[e][d] * cw_s[e];
            tr = fminf(10.0f, fmaxf(-10.0f, tr));
            atomicAdd(&g_agg_c[(long)row_s[e] * 3 + d], tr);
        }
    }
    if (t < EPB) {
        long eg = e0 + t;
        if (eg < E) atomicAdd(&g_cnt[row_s[t]], 1.0f);
    }
}

// ---------------- node kernel: h_out = h + node_mlp([h, agg]) ----------------
// Aliasing: rows 0-127 h (kept for residual), rows 128-255 agg -> hid.
__global__ __launch_bounds__(64, 10) void node_kernel(
    const float* __restrict__ h,
    const float* __restrict__ Wn1, const float* __restrict__ bn1,
    const float* __restrict__ Wn2, const float* __restrict__ bn2,
    float* __restrict__ h_out, int N)
{
    __shared__ __align__(16) float in_t[256][RS];

    const int t = threadIdx.x;     // 0..63
    const int f2 = 2 * t;
    const long n0 = (long)blockIdx.x * EPB;

#pragma unroll
    for (int e = 0; e < EPB; e++) {
        long n = n0 + e;
        if (n >= N) n = N - 1;
        long nb = n * D;
        in_t[t][e]        = h[nb + t];
        in_t[t + 64][e]   = h[nb + t + 64];
        in_t[128 + t][e]  = g_agg_h[nb + t];
        in_t[192 + t][e]  = g_agg_h[nb + t + 64];
    }
    __syncthreads();

    ull a0[8], a1[8];
#pragma unroll
    for (int j = 0; j < 8; j++) { a0[j] = 0ull; a1[j] = 0ull; }
    mm2<256>(in_t, Wn1, f2, a0, a1);
    __syncthreads();   // reads done; rows 128-255 become hid storage
    {
        float2 b = *(const float2*)&bn1[f2];
        ull b0 = dup2(b.x), b1 = dup2(b.y);
#pragma unroll
        for (int j = 0; j < 8; j++) {
            ADD2(a0[j], a0[j], b0); st2(&in_t[128 + f2][2 * j], silu2(a0[j]));
            ADD2(a1[j], a1[j], b1); st2(&in_t[129 + f2][2 * j], silu2(a1[j]));
        }
    }
    __syncthreads();

#pragma unroll
    for (int j = 0; j < 8; j++) { a0[j] = 0ull; a1[j] = 0ull; }
    mm2<128>((const float (*)[RS])(in_t + 128), Wn2, f2, a0, a1);
    {
        float2 b = *(const float2*)&bn2[f2];
#pragma unroll
        for (int j = 0; j < 8; j++) {
            float2 hA = *(const float2*)&in_t[f2][2 * j];       // h[nA..nB] feature f2
            float2 hB = *(const float2*)&in_t[f2 + 1][2 * j];   // feature f2+1
            long nA = n0 + 2 * j, nB = nA + 1;
            if (nA < N)
                *(float2*)&h_out[nA * D + f2] =
                    make_float2(hA.x + lo2(a0[j]) + b.x, hB.x + lo2(a1[j]) + b.y);
            if (nB < N)
                *(float2*)&h_out[nB * D + f2] =
                    make_float2(hA.y + hi2(a0[j]) + b.x, hB.y + hi2(a1[j]) + b.y);
        }
    }
}

// ---------------- coord finalize: coord + clip(agg_c / max(cnt,1), +/-10) ----
__global__ void coord_kernel(const float* __restrict__ coord,
                             float* __restrict__ coord_out, int N)
{
    int i = blockIdx.x * blockDim.x + threadIdx.x;
    if (i < N * 3) {
        int n = i / 3;
        float m = g_agg_c[i] / fmaxf(g_cnt[n], 1.0f);
        m = fminf(10.0f, fmaxf(-10.0f, m));
        coord_out[i] = coord[i] + m;
    }
}

// ---------------- launch ----------------
extern "C" void kernel_launch(void* const* d_in, const int* in_sizes, int n_in,
                              void* d_out, int out_size)
{
    const float* h     = (const float*)d_in[0];
    const void*  ei    = d_in[1];
    const float* coord = (const float*)d_in[2];
    const float* We1   = (const float*)d_in[3];
    const float* be1   = (const float*)d_in[4];
    const float* We2   = (const float*)d_in[5];
    const float* be2   = (const float*)d_in[6];
    const float* Watt  = (const float*)d_in[7];
    const float* batt  = (const float*)d_in[8];
    const float* Wc1   = (const float*)d_in[9];
    const float* bc1   = (const float*)d_in[10];
    const float* Wc2   = (const float*)d_in[11];
    const float* Wn1   = (const float*)d_in[12];
    const float* bn1   = (const float*)d_in[13];
    const float* Wn2   = (const float*)d_in[14];
    const float* bn2   = (const float*)d_in[15];

    const int N = in_sizes[0] / D;
    const int E = in_sizes[1] / 2;

    float* out       = (float*)d_out;
    float* h_out     = out;
    float* coord_out = out + (long)N * D;
    float* out_ef    = out + (long)N * D + (long)N * 3;

    detect_kernel<<<1, 32>>>((const int*)ei);
    zero_kernel<<<1024, 256>>>(N);

    int pb = (N + EPB - 1) / EPB;
    pre_kernel<<<pb, 64>>>(h, We1, N);

    int eb = (E + EPB - 1) / EPB;
    edge_kernel<<<eb, 64>>>(ei, coord,
                            We1, be1, We2, be2, Watt, batt,
                            Wc1, bc1, Wc2, out_ef, E);

    int nb = (N + EPB - 1) / EPB;
    node_kernel<<<nb, 64>>>(h, Wn1, bn1, Wn2, bn2, h_out, N);

    coord_kernel<<<(N * 3 + 255) / 256, 256>>>(coord, coord_out, N);
}